// round 2
// baseline (speedup 1.0000x reference)
#include <cuda_runtime.h>
#include <cuda_bf16.h>
#include <cstddef>

#define NN   50000
#define EE   800000
#define INF  512
#define H1F  256
#define H2F  128
#define NEG  0.2f

// ---------------- scratch (device globals; no allocation allowed) ----------------
__device__ int   g_is64;
__device__ int   g_src[EE];
__device__ int   g_dst[EE];
__device__ float g_deg[NN];
__device__ float g_dinv[NN];
__device__ float g_coef[EE];
__device__ float g_H1[NN * H1F];   // X @ W1
__device__ float g_A1[NN * H1F];   // layer-1 aggregate / activated Z
__device__ float g_H2[NN * H2F];   // Z @ W2
__device__ float g_A2[NN * H2F];   // layer-2 aggregate

// ---------------- edge dtype detection + conversion ----------------
// View edge_index as int32[2E] (safe under both int32 and int64 layouts).
// If the underlying data is int64 little-endian with node ids < 2^31, every
// odd 32-bit word of the first 1024 entries is a zero high-word. If it is
// int32, those words are random node ids (all-zero probability ~0).
__global__ void k_detect(const int* __restrict__ w) {
    __shared__ int nz;
    if (threadIdx.x == 0) nz = 0;
    __syncthreads();
    for (int i = threadIdx.x; i < 1024; i += blockDim.x)
        if (w[2 * i + 1] != 0) atomicOr(&nz, 1);
    __syncthreads();
    if (threadIdx.x == 0) g_is64 = (nz == 0) ? 1 : 0;
}

__global__ void k_init_deg() {
    int i = blockIdx.x * blockDim.x + threadIdx.x;
    if (i < NN) g_deg[i] = 1.0f;   // +1 self loop
}

// convert to int32 src/dst and accumulate degree in one pass
__global__ void k_convert(const int* __restrict__ w) {
    int e = blockIdx.x * blockDim.x + threadIdx.x;
    if (e >= EE) return;
    int s, d;
    if (g_is64) {
        s = w[2 * e];               // low word of int64 src[e]
        d = w[2 * EE + 2 * e];      // low word of int64 dst[e]
    } else {
        s = w[e];
        d = w[EE + e];
    }
    g_src[e] = s;
    g_dst[e] = d;
    atomicAdd(&g_deg[d], 1.0f);
}

__global__ void k_dinv() {
    int i = blockIdx.x * blockDim.x + threadIdx.x;
    if (i < NN) g_dinv[i] = rsqrtf(g_deg[i]);
}

__global__ void k_coef() {
    int e = blockIdx.x * blockDim.x + threadIdx.x;
    if (e < EE) g_coef[e] = g_dinv[g_src[e]] * g_dinv[g_dst[e]];
}

// ---------------- fp32 tiled GEMM: C[M,N] = A[M,K] @ B[K,N] ----------------
// 64x64 tile, BK=16, 256 threads, 4x4 micro-tile per thread.
__device__ __forceinline__ void gemm_body(const float* __restrict__ A,
                                          const float* __restrict__ B,
                                          float* __restrict__ C,
                                          int M, int N, int K) {
    __shared__ float As[16][65];
    __shared__ float Bs[16][68];
    const int tid  = threadIdx.x;
    const int row0 = blockIdx.y * 64;
    const int col0 = blockIdx.x * 64;
    const int ty = tid >> 4;          // 0..15
    const int tx = tid & 15;          // 0..15
    const int ar = tid >> 2;          // 0..63  (A tile row)
    const int ac = (tid & 3) << 2;    // 0,4,8,12 (A tile k-col)
    const int br = tid >> 4;          // 0..15  (B tile k-row)
    const int bc = (tid & 15) << 2;   // 0..60  (B tile col)

    float acc[4][4];
#pragma unroll
    for (int i = 0; i < 4; i++)
#pragma unroll
        for (int j = 0; j < 4; j++) acc[i][j] = 0.0f;

    for (int kt = 0; kt < K; kt += 16) {
        float4 av = make_float4(0.f, 0.f, 0.f, 0.f);
        int arow = row0 + ar;
        if (arow < M) av = *(const float4*)(A + (size_t)arow * K + kt + ac);
        As[ac + 0][ar] = av.x;
        As[ac + 1][ar] = av.y;
        As[ac + 2][ar] = av.z;
        As[ac + 3][ar] = av.w;

        float4 bv = *(const float4*)(B + (size_t)(kt + br) * N + col0 + bc);
        *(float4*)&Bs[br][bc] = bv;
        __syncthreads();

#pragma unroll
        for (int k = 0; k < 16; k++) {
            float a0 = As[k][ty * 4 + 0];
            float a1 = As[k][ty * 4 + 1];
            float a2 = As[k][ty * 4 + 2];
            float a3 = As[k][ty * 4 + 3];
            float4 b4 = *(float4*)&Bs[k][tx * 4];
            acc[0][0] += a0 * b4.x; acc[0][1] += a0 * b4.y; acc[0][2] += a0 * b4.z; acc[0][3] += a0 * b4.w;
            acc[1][0] += a1 * b4.x; acc[1][1] += a1 * b4.y; acc[1][2] += a1 * b4.z; acc[1][3] += a1 * b4.w;
            acc[2][0] += a2 * b4.x; acc[2][1] += a2 * b4.y; acc[2][2] += a2 * b4.z; acc[2][3] += a2 * b4.w;
            acc[3][0] += a3 * b4.x; acc[3][1] += a3 * b4.y; acc[3][2] += a3 * b4.z; acc[3][3] += a3 * b4.w;
        }
        __syncthreads();
    }

#pragma unroll
    for (int i = 0; i < 4; i++) {
        int row = row0 + ty * 4 + i;
        if (row < M) {
            float4 o = make_float4(acc[i][0], acc[i][1], acc[i][2], acc[i][3]);
            *(float4*)(C + (size_t)row * N + col0 + tx * 4) = o;
        }
    }
}

__global__ void k_gemm1(const float* __restrict__ X, const float* __restrict__ W) {
    gemm_body(X, W, g_H1, NN, H1F, INF);
}
__global__ void k_gemm2(const float* __restrict__ W) {
    gemm_body(g_A1, W, g_H2, NN, H2F, H1F);
}

// ---------------- self-loop init: A = dinv^2 * H ----------------
template <int C>
__device__ __forceinline__ void init_body(const float* __restrict__ H, float* __restrict__ A) {
    int i = blockIdx.x * blockDim.x + threadIdx.x;   // over NN*C/4 float4s
    if (i >= NN * (C / 4)) return;
    int node = i / (C / 4);
    float s = g_dinv[node];
    s = s * s;
    float4 h = ((const float4*)H)[i];
    ((float4*)A)[i] = make_float4(h.x * s, h.y * s, h.z * s, h.w * s);
}
__global__ void k_init1() { init_body<H1F>(g_H1, g_A1); }
__global__ void k_init2() { init_body<H2F>(g_H2, g_A2); }

// ---------------- edge scatter: A[dst] += coef[e] * H[src] ----------------
template <int C>
__device__ __forceinline__ void scatter_body(const float* __restrict__ H,
                                             float* __restrict__ A) {
    const int CH = C / 4;
    int idx = blockIdx.x * blockDim.x + threadIdx.x;   // over EE*CH
    int e = idx / CH;
    if (e >= EE) return;
    int c = (idx - e * CH) * 4;
    int src = g_src[e];
    int dst = g_dst[e];
    float k = g_coef[e];
    float4 v = *(const float4*)(H + (size_t)src * C + c);
    float* o = A + (size_t)dst * C + c;
    atomicAdd(o + 0, v.x * k);
    atomicAdd(o + 1, v.y * k);
    atomicAdd(o + 2, v.z * k);
    atomicAdd(o + 3, v.w * k);
}
__global__ void k_scatter1() { scatter_body<H1F>(g_H1, g_A1); }
__global__ void k_scatter2() { scatter_body<H2F>(g_H2, g_A2); }

// ---------------- bias + leaky relu ----------------
template <int C>
__device__ __forceinline__ void act_body(const float* __restrict__ A,
                                         const float* __restrict__ b,
                                         float* __restrict__ Out) {
    int i = blockIdx.x * blockDim.x + threadIdx.x;   // over NN*C/4 float4s
    if (i >= NN * (C / 4)) return;
    int c4 = (i % (C / 4)) * 4;
    float4 v = ((const float4*)A)[i];
    float4 bb = *(const float4*)(b + c4);
    v.x += bb.x; v.y += bb.y; v.z += bb.z; v.w += bb.w;
    v.x = v.x > 0.f ? v.x : v.x * NEG;
    v.y = v.y > 0.f ? v.y : v.y * NEG;
    v.z = v.z > 0.f ? v.z : v.z * NEG;
    v.w = v.w > 0.f ? v.w : v.w * NEG;
    ((float4*)Out)[i] = v;
}
__global__ void k_act1(const float* __restrict__ b) { act_body<H1F>(g_A1, b, g_A1); }
__global__ void k_act2(const float* __restrict__ b, float* __restrict__ out) {
    act_body<H2F>(g_A2, b, out);
}

// ---------------- launch ----------------
extern "C" void kernel_launch(void* const* d_in, const int* in_sizes, int n_in,
                              void* d_out, int out_size) {
    const float* X  = (const float*)d_in[0];
    const int*   ew = (const int*)d_in[1];   // edge_index viewed as int32 words
    const float* W1 = (const float*)d_in[2];
    const float* b1 = (const float*)d_in[3];
    const float* W2 = (const float*)d_in[4];
    const float* b2 = (const float*)d_in[5];
    float* out = (float*)d_out;

    const int T = 256;
    k_detect<<<1, 256>>>(ew);
    k_init_deg<<<(NN + T - 1) / T, T>>>();
    k_convert<<<(EE + T - 1) / T, T>>>(ew);
    k_dinv<<<(NN + T - 1) / T, T>>>();
    k_coef<<<(EE + T - 1) / T, T>>>();

    // layer 1
    dim3 g1(H1F / 64, (NN + 63) / 64);
    k_gemm1<<<g1, 256>>>(X, W1);
    k_init1<<<(NN * (H1F / 4) + T - 1) / T, T>>>();
    k_scatter1<<<(EE * (H1F / 4) + T - 1) / T, T>>>();
    k_act1<<<(NN * (H1F / 4) + T - 1) / T, T>>>(b1);

    // layer 2
    dim3 g2(H2F / 64, (NN + 63) / 64);
    k_gemm2<<<g2, 256>>>(W2);
    k_init2<<<(NN * (H2F / 4) + T - 1) / T, T>>>();
    k_scatter2<<<(EE * (H2F / 4) + T - 1) / T, T>>>();
    k_act2<<<(NN * (H2F / 4) + T - 1) / T, T>>>(b2, out);
}

// round 3
// speedup vs baseline: 3.1316x; 3.1316x over previous
#include <cuda_runtime.h>
#include <cuda_bf16.h>
#include <cstddef>

#define NN   50000
#define EE   800000
#define INF  512
#define H1F  256
#define H2F  128
#define NEG  0.2f
#define NBLK 196   // ceil(NN/256)

// ---------------- scratch (device globals) ----------------
__device__ int   g_is64;
__device__ int   g_src[EE];
__device__ int   g_dst[EE];
__device__ int   g_cnt[NN];        // in-degree (no self loop)
__device__ int   g_cur[NN];        // placement cursor
__device__ int   g_rowptr[NN + 1];
__device__ int   g_bsum[NBLK];
__device__ int   g_boff[NBLK];
__device__ int   g_csrc[EE];       // CSR src per dst-sorted edge
__device__ float g_ccoef[EE];      // CSR coef
__device__ float g_dinv[NN];
__device__ float g_H1[NN * H1F];   // X @ W1
__device__ float g_A1[NN * H1F];   // layer-1 activated output
__device__ float g_H2[NN * H2F];   // A1 @ W2

// ---------------- edge dtype detection ----------------
__global__ void k_detect(const int* __restrict__ w) {
    __shared__ int nz;
    if (threadIdx.x == 0) nz = 0;
    __syncthreads();
    for (int i = threadIdx.x; i < 1024; i += blockDim.x)
        if (w[2 * i + 1] != 0) atomicOr(&nz, 1);
    __syncthreads();
    if (threadIdx.x == 0) g_is64 = (nz == 0) ? 1 : 0;
}

__global__ void k_zero() {
    int i = blockIdx.x * blockDim.x + threadIdx.x;
    if (i < NN) { g_cnt[i] = 0; g_cur[i] = 0; }
}

// convert edge words to int32 src/dst + histogram dst
__global__ void k_convert(const int* __restrict__ w) {
    int e = blockIdx.x * blockDim.x + threadIdx.x;
    if (e >= EE) return;
    int s, d;
    if (g_is64) { s = w[2 * e]; d = w[2 * EE + 2 * e]; }
    else        { s = w[e];     d = w[EE + e]; }
    g_src[e] = s;
    g_dst[e] = d;
    atomicAdd(&g_cnt[d], 1);
}

// ---------------- 3-kernel exclusive scan of g_cnt -> g_rowptr ----------------
__global__ void k_scan1() {   // per-block sums
    __shared__ int sh[256];
    int tid = threadIdx.x;
    int i = blockIdx.x * 256 + tid;
    sh[tid] = (i < NN) ? g_cnt[i] : 0;
    __syncthreads();
    for (int ofs = 128; ofs > 0; ofs >>= 1) {
        if (tid < ofs) sh[tid] += sh[tid + ofs];
        __syncthreads();
    }
    if (tid == 0) g_bsum[blockIdx.x] = sh[0];
}

__global__ void k_scan2() {   // exclusive scan of block sums (1 block)
    __shared__ int sh[256];
    int tid = threadIdx.x;
    int v = (tid < NBLK) ? g_bsum[tid] : 0;
    sh[tid] = v;
    __syncthreads();
    for (int ofs = 1; ofs < 256; ofs <<= 1) {
        int t = (tid >= ofs) ? sh[tid - ofs] : 0;
        __syncthreads();
        sh[tid] += t;
        __syncthreads();
    }
    if (tid < NBLK) g_boff[tid] = sh[tid] - v;
}

__global__ void k_scan3() {   // local exclusive scan + block offset
    __shared__ int sh[256];
    int tid = threadIdx.x;
    int i = blockIdx.x * 256 + tid;
    int v = (i < NN) ? g_cnt[i] : 0;
    sh[tid] = v;
    __syncthreads();
    for (int ofs = 1; ofs < 256; ofs <<= 1) {
        int t = (tid >= ofs) ? sh[tid - ofs] : 0;
        __syncthreads();
        sh[tid] += t;
        __syncthreads();
    }
    if (i < NN) g_rowptr[i] = sh[tid] - v + g_boff[blockIdx.x];
    if (blockIdx.x == 0 && tid == 0) g_rowptr[NN] = EE;
}

__global__ void k_dinv() {
    int i = blockIdx.x * blockDim.x + threadIdx.x;
    if (i < NN) g_dinv[i] = rsqrtf((float)g_cnt[i] + 1.0f);
}

__global__ void k_place() {
    int e = blockIdx.x * blockDim.x + threadIdx.x;
    if (e >= EE) return;
    int s = g_src[e], d = g_dst[e];
    float cf = g_dinv[s] * g_dinv[d];
    int pos = g_rowptr[d] + atomicAdd(&g_cur[d], 1);
    g_csrc[pos]  = s;
    g_ccoef[pos] = cf;
}

// ---------------- TF32 tensor-core GEMM: C[M,N] = A[M,K] @ B[K,N] ----------------
// block tile 128x64, BK=32, 256 threads (8 warps: 4 along M, 2 along N),
// warp tile 32x32 = 2(m16) x 4(n8) mma fragments.
__device__ __forceinline__ unsigned f2tf32(float x) {
    unsigned r;
    asm("cvt.rna.tf32.f32 %0, %1;" : "=r"(r) : "f"(x));
    return r;
}

__device__ __forceinline__ void mma_tf32(float& c0, float& c1, float& c2, float& c3,
                                         unsigned a0, unsigned a1, unsigned a2, unsigned a3,
                                         unsigned b0, unsigned b1) {
    asm volatile(
        "mma.sync.aligned.m16n8k8.row.col.f32.tf32.tf32.f32 "
        "{%0,%1,%2,%3},{%4,%5,%6,%7},{%8,%9},{%0,%1,%2,%3};"
        : "+f"(c0), "+f"(c1), "+f"(c2), "+f"(c3)
        : "r"(a0), "r"(a1), "r"(a2), "r"(a3), "r"(b0), "r"(b1));
}

__device__ __forceinline__ void gemm_tf32_body(const float* __restrict__ A,
                                               const float* __restrict__ B,
                                               float* __restrict__ C,
                                               int M, int N, int K) {
    __shared__ unsigned As[128][36];  // [row][k], stride 36 -> conflict-free frags
    __shared__ unsigned Bs[32][68];   // [k][col], stride 68

    const int tid  = threadIdx.x;
    const int warp = tid >> 5;
    const int lane = tid & 31;
    const int wm = warp & 3;    // 0..3  (M offset 32*wm)
    const int wn = warp >> 2;   // 0..1  (N offset 32*wn)
    const int g  = lane >> 2;   // groupID 0..7
    const int tg = lane & 3;    // thread-in-group 0..3
    const int row0 = blockIdx.y * 128;
    const int col0 = blockIdx.x * 64;

    float c[2][4][4];
#pragma unroll
    for (int mi = 0; mi < 2; mi++)
#pragma unroll
        for (int ni = 0; ni < 4; ni++)
#pragma unroll
            for (int q = 0; q < 4; q++) c[mi][ni][q] = 0.0f;

    for (int kt = 0; kt < K; kt += 32) {
        // load A tile: 128 x 32 = 1024 float4s
#pragma unroll
        for (int it = 0; it < 4; it++) {
            int f = it * 256 + tid;
            int r = f >> 3;
            int kc = (f & 7) << 2;
            float4 v = make_float4(0.f, 0.f, 0.f, 0.f);
            if (row0 + r < M) v = *(const float4*)(A + (size_t)(row0 + r) * K + kt + kc);
            As[r][kc + 0] = f2tf32(v.x);
            As[r][kc + 1] = f2tf32(v.y);
            As[r][kc + 2] = f2tf32(v.z);
            As[r][kc + 3] = f2tf32(v.w);
        }
        // load B tile: 32 x 64 = 512 float4s
#pragma unroll
        for (int it = 0; it < 2; it++) {
            int f = it * 256 + tid;
            int r = f >> 4;
            int cc = (f & 15) << 2;
            float4 v = *(const float4*)(B + (size_t)(kt + r) * N + col0 + cc);
            Bs[r][cc + 0] = f2tf32(v.x);
            Bs[r][cc + 1] = f2tf32(v.y);
            Bs[r][cc + 2] = f2tf32(v.z);
            Bs[r][cc + 3] = f2tf32(v.w);
        }
        __syncthreads();

#pragma unroll
        for (int ks = 0; ks < 4; ks++) {
            int k0 = ks * 8;
            unsigned a[2][4], b[4][2];
#pragma unroll
            for (int mi = 0; mi < 2; mi++) {
                int r = wm * 32 + mi * 16 + g;
                a[mi][0] = As[r][k0 + tg];
                a[mi][1] = As[r + 8][k0 + tg];
                a[mi][2] = As[r][k0 + tg + 4];
                a[mi][3] = As[r + 8][k0 + tg + 4];
            }
#pragma unroll
            for (int ni = 0; ni < 4; ni++) {
                int cc = wn * 32 + ni * 8 + g;
                b[ni][0] = Bs[k0 + tg][cc];
                b[ni][1] = Bs[k0 + tg + 4][cc];
            }
#pragma unroll
            for (int mi = 0; mi < 2; mi++)
#pragma unroll
                for (int ni = 0; ni < 4; ni++)
                    mma_tf32(c[mi][ni][0], c[mi][ni][1], c[mi][ni][2], c[mi][ni][3],
                             a[mi][0], a[mi][1], a[mi][2], a[mi][3],
                             b[ni][0], b[ni][1]);
        }
        __syncthreads();
    }

    // store C fragments
#pragma unroll
    for (int mi = 0; mi < 2; mi++) {
        int r0 = row0 + wm * 32 + mi * 16 + g;
#pragma unroll
        for (int ni = 0; ni < 4; ni++) {
            int cc = col0 + wn * 32 + ni * 8 + 2 * tg;
            if (r0 < M) {
                C[(size_t)r0 * N + cc]     = c[mi][ni][0];
                C[(size_t)r0 * N + cc + 1] = c[mi][ni][1];
            }
            if (r0 + 8 < M) {
                C[(size_t)(r0 + 8) * N + cc]     = c[mi][ni][2];
                C[(size_t)(r0 + 8) * N + cc + 1] = c[mi][ni][3];
            }
        }
    }
}

__global__ void k_gemm1(const float* __restrict__ X, const float* __restrict__ W) {
    gemm_tf32_body(X, W, g_H1, NN, H1F, INF);
}
__global__ void k_gemm2(const float* __restrict__ W) {
    gemm_tf32_body(g_A1, W, g_H2, NN, H2F, H1F);
}

// ---------------- fused CSR aggregate + self-loop + bias + leakyReLU ----------------
// one block per node, C threads (one channel each)
template <int C>
__device__ __forceinline__ void agg_body(const float* __restrict__ H,
                                         const float* __restrict__ bias,
                                         float* __restrict__ Out) {
    __shared__ int   sh_src[128];
    __shared__ float sh_cf[128];
    const int n   = blockIdx.x;
    const int tid = threadIdx.x;
    const int beg = g_rowptr[n];
    const int end = g_rowptr[n + 1];

    float dv = g_dinv[n];
    float acc = dv * dv * H[(size_t)n * C + tid];   // self loop

    for (int jb = beg; jb < end; jb += 128) {
        int m = end - jb;
        if (m > 128) m = 128;
        if (tid < m) {
            sh_src[tid] = g_csrc[jb + tid];
            sh_cf[tid]  = g_ccoef[jb + tid];
        }
        __syncthreads();
        for (int j = 0; j < m; j++)
            acc += sh_cf[j] * H[(size_t)sh_src[j] * C + tid];
        __syncthreads();
    }

    acc += bias[tid];
    acc = acc > 0.f ? acc : acc * NEG;
    Out[(size_t)n * C + tid] = acc;
}

__global__ void k_agg1(const float* __restrict__ b) { agg_body<H1F>(g_H1, b, g_A1); }
__global__ void k_agg2(const float* __restrict__ b, float* __restrict__ out) {
    agg_body<H2F>(g_H2, b, out);
}

// ---------------- launch ----------------
extern "C" void kernel_launch(void* const* d_in, const int* in_sizes, int n_in,
                              void* d_out, int out_size) {
    const float* X  = (const float*)d_in[0];
    const int*   ew = (const int*)d_in[1];
    const float* W1 = (const float*)d_in[2];
    const float* b1 = (const float*)d_in[3];
    const float* W2 = (const float*)d_in[4];
    const float* b2 = (const float*)d_in[5];
    float* out = (float*)d_out;

    const int T = 256;
    // preprocessing: CSR build
    k_detect<<<1, 256>>>(ew);
    k_zero<<<NBLK, T>>>();
    k_convert<<<(EE + T - 1) / T, T>>>(ew);
    k_scan1<<<NBLK, T>>>();
    k_scan2<<<1, T>>>();
    k_scan3<<<NBLK, T>>>();
    k_dinv<<<NBLK, T>>>();
    k_place<<<(EE + T - 1) / T, T>>>();

    // layer 1
    dim3 g1(H1F / 64, (NN + 127) / 128);
    k_gemm1<<<g1, 256>>>(X, W1);
    k_agg1<<<NN, H1F>>>(b1);

    // layer 2
    dim3 g2(H2F / 64, (NN + 127) / 128);
    k_gemm2<<<g2, 256>>>(W2);
    k_agg2<<<NN, H2F>>>(b2, out);
}

// round 7
// speedup vs baseline: 3.1749x; 1.0138x over previous
#include <cuda_runtime.h>
#include <cuda_bf16.h>
#include <cstddef>

#define NN   50000
#define EE   800000
#define INF  512
#define H1F  256
#define H2F  128
#define NEG  0.2f
#define NBLK 196   // ceil(NN/256)

// ---------------- scratch (device globals) ----------------
__device__ int   g_is64;
__device__ int   g_src[EE];
__device__ int   g_dst[EE];
__device__ int   g_cnt[NN];
__device__ int   g_cur[NN];
__device__ int   g_rowptr[NN + 1];
__device__ int   g_bsum[NBLK];
__device__ float g_dinv[NN];
__device__ int   g_csrc[EE];
__device__ float g_ccoef[EE];
__device__ float g_H1[NN * H1F];
__device__ float g_A1[NN * H1F];
__device__ float g_H2[NN * H2F];

// ---------------- zero + edge dtype detect (merged) ----------------
__global__ void k_zerodet(const int* __restrict__ w) {
    int i = blockIdx.x * blockDim.x + threadIdx.x;
    if (i < NN) { g_cnt[i] = 0; g_cur[i] = 0; }
    if (blockIdx.x == 0) {
        __shared__ int nz;
        if (threadIdx.x == 0) nz = 0;
        __syncthreads();
        for (int j = threadIdx.x; j < 1024; j += blockDim.x)
            if (w[2 * j + 1] != 0) atomicOr(&nz, 1);
        __syncthreads();
        if (threadIdx.x == 0) g_is64 = (nz == 0) ? 1 : 0;
    }
}

__global__ void k_convert(const int* __restrict__ w) {
    int e = blockIdx.x * blockDim.x + threadIdx.x;
    if (e >= EE) return;
    int s, d;
    if (g_is64) { s = w[2 * e]; d = w[2 * EE + 2 * e]; }
    else        { s = w[e];     d = w[EE + e]; }
    g_src[e] = s;
    g_dst[e] = d;
    atomicAdd(&g_cnt[d], 1);
}

__global__ void k_scan1() {
    __shared__ int sh[256];
    int tid = threadIdx.x;
    int i = blockIdx.x * 256 + tid;
    sh[tid] = (i < NN) ? g_cnt[i] : 0;
    __syncthreads();
    for (int ofs = 128; ofs > 0; ofs >>= 1) {
        if (tid < ofs) sh[tid] += sh[tid + ofs];
        __syncthreads();
    }
    if (tid == 0) g_bsum[blockIdx.x] = sh[0];
}

__global__ void k_scan23() {
    __shared__ int sh[256];
    __shared__ int boff_sh;
    int tid = threadIdx.x;
    int b = blockIdx.x;
    sh[tid] = (tid < b) ? g_bsum[tid] : 0;
    __syncthreads();
    for (int ofs = 128; ofs > 0; ofs >>= 1) {
        if (tid < ofs) sh[tid] += sh[tid + ofs];
        __syncthreads();
    }
    if (tid == 0) boff_sh = sh[0];
    __syncthreads();
    int boff = boff_sh;
    __syncthreads();
    int i = b * 256 + tid;
    int v = (i < NN) ? g_cnt[i] : 0;
    sh[tid] = v;
    __syncthreads();
    for (int ofs = 1; ofs < 256; ofs <<= 1) {
        int t = (tid >= ofs) ? sh[tid - ofs] : 0;
        __syncthreads();
        sh[tid] += t;
        __syncthreads();
    }
    if (i < NN) {
        g_rowptr[i] = sh[tid] - v + boff;
        g_dinv[i] = rsqrtf((float)v + 1.0f);
    }
    if (b == 0 && tid == 0) g_rowptr[NN] = EE;
}

__global__ void k_place() {
    int e = blockIdx.x * blockDim.x + threadIdx.x;
    if (e >= EE) return;
    int s = g_src[e], d = g_dst[e];
    float cf = g_dinv[s] * g_dinv[d];
    int pos = g_rowptr[d] + atomicAdd(&g_cur[d], 1);
    g_csrc[pos]  = s;
    g_ccoef[pos] = cf;
}

// ---------------- TF32 tensor-core GEMM, cp.async 2-stage, 128x128 tile ----------------
// 256 threads (8 warps: 4 M x 2 N), warp tile 32x64. RNA rounding at fragment load.
#define AS_STRIDE 36
#define BS_STRIDE 136
#define AS_ELEMS  (128 * AS_STRIDE)   // 4608
#define BS_ELEMS  (32 * BS_STRIDE)    // 4352
#define GEMM_SMEM ((2 * (AS_ELEMS + BS_ELEMS)) * 4)   // 71680 B

__device__ __forceinline__ void cp16(void* dst_smem, const void* src, int sz) {
    unsigned d = (unsigned)__cvta_generic_to_shared(dst_smem);
    asm volatile("cp.async.cg.shared.global [%0], [%1], 16, %2;\n"
                 :: "r"(d), "l"(src), "r"(sz));
}
__device__ __forceinline__ void cp_commit() {
    asm volatile("cp.async.commit_group;\n");
}
__device__ __forceinline__ void cp_wait1() {
    asm volatile("cp.async.wait_group 1;\n");
}
__device__ __forceinline__ unsigned rna(float x) {
    unsigned r;
    asm("cvt.rna.tf32.f32 %0, %1;" : "=r"(r) : "f"(x));
    return r;
}

__device__ __forceinline__ void mma_tf32(float& c0, float& c1, float& c2, float& c3,
                                         unsigned a0, unsigned a1, unsigned a2, unsigned a3,
                                         unsigned b0, unsigned b1) {
    asm volatile(
        "mma.sync.aligned.m16n8k8.row.col.f32.tf32.tf32.f32 "
        "{%0,%1,%2,%3},{%4,%5,%6,%7},{%8,%9},{%0,%1,%2,%3};"
        : "+f"(c0), "+f"(c1), "+f"(c2), "+f"(c3)
        : "r"(a0), "r"(a1), "r"(a2), "r"(a3), "r"(b0), "r"(b1));
}

__device__ __forceinline__ void gemm_body(const float* __restrict__ A,
                                          const float* __restrict__ B,
                                          float* __restrict__ C,
                                          int M, int N, int K) {
    extern __shared__ float sm[];
    float* As = sm;                       // [2][128][AS_STRIDE]
    float* Bs = sm + 2 * AS_ELEMS;        // [2][32][BS_STRIDE]

    const int tid  = threadIdx.x;
    const int warp = tid >> 5;
    const int lane = tid & 31;
    const int wm = warp & 3;    // M offset 32*wm
    const int wn = warp >> 2;   // N offset 64*wn
    const int g  = lane >> 2;
    const int tg = lane & 3;
    const int row0 = blockIdx.y * 128;
    const int col0 = blockIdx.x * 128;

    const int ar  = tid >> 3;           // 0..31
    const int akc = (tid & 7) << 2;
    const int br  = tid >> 5;           // 0..7
    const int bcc = (tid & 31) << 2;

    float c[2][8][4];
#pragma unroll
    for (int mi = 0; mi < 2; mi++)
#pragma unroll
        for (int ni = 0; ni < 8; ni++)
#pragma unroll
            for (int q = 0; q < 4; q++) c[mi][ni][q] = 0.0f;

    const int KT = K >> 5;

    auto fill = [&](int s, int kt) {
        float* as = As + s * AS_ELEMS;
        float* bs = Bs + s * BS_ELEMS;
#pragma unroll
        for (int it = 0; it < 4; it++) {
            int r = ar + it * 32;
            int sz = (row0 + r < M) ? 16 : 0;
            cp16(as + r * AS_STRIDE + akc,
                 A + (size_t)(row0 + r) * K + kt + akc, sz);
        }
#pragma unroll
        for (int it = 0; it < 4; it++) {
            int r = br + it * 8;
            cp16(bs + r * BS_STRIDE + bcc,
                 B + (size_t)(kt + r) * N + col0 + bcc, 16);
        }
    };

    fill(0, 0);
    cp_commit();

    for (int kti = 0; kti < KT; kti++) {
        if (kti + 1 < KT) fill((kti + 1) & 1, (kti + 1) * 32);
        cp_commit();
        cp_wait1();
        __syncthreads();

        const float* as = As + (kti & 1) * AS_ELEMS;
        const float* bs = Bs + (kti & 1) * BS_ELEMS;
#pragma unroll
        for (int ks = 0; ks < 4; ks++) {
            int k0 = ks * 8;
            unsigned a[2][4], b[8][2];
#pragma unroll
            for (int mi = 0; mi < 2; mi++) {
                int r = wm * 32 + mi * 16 + g;
                a[mi][0] = rna(as[r * AS_STRIDE + k0 + tg]);
                a[mi][1] = rna(as[(r + 8) * AS_STRIDE + k0 + tg]);
                a[mi][2] = rna(as[r * AS_STRIDE + k0 + tg + 4]);
                a[mi][3] = rna(as[(r + 8) * AS_STRIDE + k0 + tg + 4]);
            }
#pragma unroll
            for (int ni = 0; ni < 8; ni++) {
                int cc = wn * 64 + ni * 8 + g;
                b[ni][0] = rna(bs[(k0 + tg) * BS_STRIDE + cc]);
                b[ni][1] = rna(bs[(k0 + tg + 4) * BS_STRIDE + cc]);
            }
#pragma unroll
            for (int mi = 0; mi < 2; mi++)
#pragma unroll
                for (int ni = 0; ni < 8; ni++)
                    mma_tf32(c[mi][ni][0], c[mi][ni][1], c[mi][ni][2], c[mi][ni][3],
                             a[mi][0], a[mi][1], a[mi][2], a[mi][3],
                             b[ni][0], b[ni][1]);
        }
        __syncthreads();
    }

#pragma unroll
    for (int mi = 0; mi < 2; mi++) {
        int r0 = row0 + wm * 32 + mi * 16 + g;
#pragma unroll
        for (int ni = 0; ni < 8; ni++) {
            int cc = col0 + wn * 64 + ni * 8 + 2 * tg;
            if (r0 < M) {
                C[(size_t)r0 * N + cc]     = c[mi][ni][0];
                C[(size_t)r0 * N + cc + 1] = c[mi][ni][1];
            }
            if (r0 + 8 < M) {
                C[(size_t)(r0 + 8) * N + cc]     = c[mi][ni][2];
                C[(size_t)(r0 + 8) * N + cc + 1] = c[mi][ni][3];
            }
        }
    }
}

__global__ void k_gemm1(const float* __restrict__ X, const float* __restrict__ W) {
    gemm_body(X, W, g_H1, NN, H1F, INF);
}
__global__ void k_gemm2(const float* __restrict__ W) {
    gemm_body(g_A1, W, g_H2, NN, H2F, H1F);
}

// ---------------- fused CSR aggregate + self-loop + bias + leakyReLU ----------------
template <int C>
__device__ __forceinline__ void agg_body(const float* __restrict__ H,
                                         const float* __restrict__ bias,
                                         float* __restrict__ Out) {
    __shared__ int   sh_src[256];
    __shared__ float sh_cf[256];
    const int n   = blockIdx.x;
    const int tid = threadIdx.x;
    const int beg = g_rowptr[n];
    const int end = g_rowptr[n + 1];

    float dv = g_dinv[n];
    float a0 = dv * dv * H[(size_t)n * C + tid];
    float a1 = 0.f, a2 = 0.f, a3 = 0.f;

    for (int jb = beg; jb < end; jb += 256) {
        int m = end - jb;
        if (m > 256) m = 256;
        for (int t = tid; t < m; t += C) {
            sh_src[t] = g_csrc[jb + t];
            sh_cf[t]  = g_ccoef[jb + t];
        }
        __syncthreads();
        int j = 0;
        for (; j + 4 <= m; j += 4) {
            a0 += sh_cf[j]     * H[(size_t)sh_src[j]     * C + tid];
            a1 += sh_cf[j + 1] * H[(size_t)sh_src[j + 1] * C + tid];
            a2 += sh_cf[j + 2] * H[(size_t)sh_src[j + 2] * C + tid];
            a3 += sh_cf[j + 3] * H[(size_t)sh_src[j + 3] * C + tid];
        }
        for (; j < m; j++)
            a0 += sh_cf[j] * H[(size_t)sh_src[j] * C + tid];
        __syncthreads();
    }

    float acc = (a0 + a1) + (a2 + a3) + bias[tid];
    acc = acc > 0.f ? acc : acc * NEG;
    Out[(size_t)n * C + tid] = acc;
}

__global__ void k_agg1(const float* __restrict__ b) { agg_body<H1F>(g_H1, b, g_A1); }
__global__ void k_agg2(const float* __restrict__ b, float* __restrict__ out) {
    agg_body<H2F>(g_H2, b, out);
}

// ---------------- launch ----------------
extern "C" void kernel_launch(void* const* d_in, const int* in_sizes, int n_in,
                              void* d_out, int out_size) {
    const float* X  = (const float*)d_in[0];
    const int*   ew = (const int*)d_in[1];
    const float* W1 = (const float*)d_in[2];
    const float* b1 = (const float*)d_in[3];
    const float* W2 = (const float*)d_in[4];
    const float* b2 = (const float*)d_in[5];
    float* out = (float*)d_out;

    cudaFuncSetAttribute(k_gemm1, cudaFuncAttributeMaxDynamicSharedMemorySize, GEMM_SMEM);
    cudaFuncSetAttribute(k_gemm2, cudaFuncAttributeMaxDynamicSharedMemorySize, GEMM_SMEM);

    const int T = 256;
    // launch order: ncu (-s 5) profiles k_gemm1
    k_zerodet<<<NBLK, T>>>(ew);                    // 0
    k_convert<<<(EE + T - 1) / T, T>>>(ew);        // 1
    k_scan1<<<NBLK, T>>>();                        // 2
    k_scan23<<<NBLK, T>>>();                       // 3
    k_place<<<(EE + T - 1) / T, T>>>();            // 4

    dim3 g1(H1F / 128, (NN + 127) / 128);
    k_gemm1<<<g1, 256, GEMM_SMEM>>>(X, W1);        // 5  <- profiled
    k_agg1<<<NN, H1F>>>(b1);                       // 6

    dim3 g2(H2F / 128, (NN + 127) / 128);
    k_gemm2<<<g2, 256, GEMM_SMEM>>>(W2);           // 7
    k_agg2<<<NN, H2F>>>(b2, out);                  // 8
}

// round 10
// speedup vs baseline: 3.3283x; 1.0483x over previous
#include <cuda_runtime.h>
#include <cuda_bf16.h>
#include <cstddef>

#define NN   50000
#define EE   800000
#define INF  512
#define H1F  256
#define H2F  128
#define NEG  0.2f
#define NBLK 196   // ceil(NN/256)

// ---------------- scratch (device globals) ----------------
__device__ int   g_is64;
__device__ int   g_cnt[NN];
__device__ int   g_cur[NN];
__device__ int   g_rowptr[NN + 1];
__device__ int   g_bsum[NBLK];
__device__ float g_dinv[NN];
__device__ int   g_csrc[EE];
__device__ float g_ccoef[EE];
__device__ float g_H1[NN * H1F];
__device__ float g_A1[NN * H1F];
__device__ float g_H2[NN * H2F];

// ---------------- zero + edge dtype detect (merged) ----------------
__global__ void k_zerodet(const int* __restrict__ w) {
    int i = blockIdx.x * blockDim.x + threadIdx.x;
    if (i < NN) { g_cnt[i] = 0; g_cur[i] = 0; }
    if (blockIdx.x == 0) {
        __shared__ int nz;
        if (threadIdx.x == 0) nz = 0;
        __syncthreads();
        for (int j = threadIdx.x; j < 1024; j += blockDim.x)
            if (w[2 * j + 1] != 0) atomicOr(&nz, 1);
        __syncthreads();
        if (threadIdx.x == 0) g_is64 = (nz == 0) ? 1 : 0;
    }
}

// histogram of dst (reads edge words directly)
__global__ void k_hist(const int* __restrict__ w) {
    int e = blockIdx.x * blockDim.x + threadIdx.x;
    if (e >= EE) return;
    int d = g_is64 ? w[2 * EE + 2 * e] : w[EE + e];
    atomicAdd(&g_cnt[d], 1);
}

__global__ void k_scan1() {
    __shared__ int sh[256];
    int tid = threadIdx.x;
    int i = blockIdx.x * 256 + tid;
    sh[tid] = (i < NN) ? g_cnt[i] : 0;
    __syncthreads();
    for (int ofs = 128; ofs > 0; ofs >>= 1) {
        if (tid < ofs) sh[tid] += sh[tid + ofs];
        __syncthreads();
    }
    if (tid == 0) g_bsum[blockIdx.x] = sh[0];
}

__global__ void k_scan23() {
    __shared__ int sh[256];
    __shared__ int boff_sh;
    int tid = threadIdx.x;
    int b = blockIdx.x;
    sh[tid] = (tid < b) ? g_bsum[tid] : 0;
    __syncthreads();
    for (int ofs = 128; ofs > 0; ofs >>= 1) {
        if (tid < ofs) sh[tid] += sh[tid + ofs];
        __syncthreads();
    }
    if (tid == 0) boff_sh = sh[0];
    __syncthreads();
    int boff = boff_sh;
    __syncthreads();
    int i = b * 256 + tid;
    int v = (i < NN) ? g_cnt[i] : 0;
    sh[tid] = v;
    __syncthreads();
    for (int ofs = 1; ofs < 256; ofs <<= 1) {
        int t = (tid >= ofs) ? sh[tid - ofs] : 0;
        __syncthreads();
        sh[tid] += t;
        __syncthreads();
    }
    if (i < NN) {
        g_rowptr[i] = sh[tid] - v + boff;
        g_dinv[i] = rsqrtf((float)v + 1.0f);
    }
    if (b == 0 && tid == 0) g_rowptr[NN] = EE;
}

__global__ void k_place(const int* __restrict__ w) {
    int e = blockIdx.x * blockDim.x + threadIdx.x;
    if (e >= EE) return;
    int s, d;
    if (g_is64) { s = w[2 * e]; d = w[2 * EE + 2 * e]; }
    else        { s = w[e];     d = w[EE + e]; }
    float cf = g_dinv[s] * g_dinv[d];
    int pos = g_rowptr[d] + atomicAdd(&g_cur[d], 1);
    g_csrc[pos]  = s;
    g_ccoef[pos] = cf;
}

// ---------------- TF32 tensor-core GEMM, cp.async 2-stage, 128x128 tile ----------------
#define AS_STRIDE 36
#define BS_STRIDE 136
#define AS_ELEMS  (128 * AS_STRIDE)
#define BS_ELEMS  (32 * BS_STRIDE)
#define GEMM_SMEM ((2 * (AS_ELEMS + BS_ELEMS)) * 4)   // 71680 B

__device__ __forceinline__ void cp16(void* dst_smem, const void* src, int sz) {
    unsigned d = (unsigned)__cvta_generic_to_shared(dst_smem);
    asm volatile("cp.async.cg.shared.global [%0], [%1], 16, %2;\n"
                 :: "r"(d), "l"(src), "r"(sz));
}
__device__ __forceinline__ void cp_commit() {
    asm volatile("cp.async.commit_group;\n");
}
__device__ __forceinline__ void cp_wait1() {
    asm volatile("cp.async.wait_group 1;\n");
}
__device__ __forceinline__ unsigned rna(float x) {
    unsigned r;
    asm("cvt.rna.tf32.f32 %0, %1;" : "=r"(r) : "f"(x));
    return r;
}

__device__ __forceinline__ void mma_tf32(float& c0, float& c1, float& c2, float& c3,
                                         unsigned a0, unsigned a1, unsigned a2, unsigned a3,
                                         unsigned b0, unsigned b1) {
    asm volatile(
        "mma.sync.aligned.m16n8k8.row.col.f32.tf32.tf32.f32 "
        "{%0,%1,%2,%3},{%4,%5,%6,%7},{%8,%9},{%0,%1,%2,%3};"
        : "+f"(c0), "+f"(c1), "+f"(c2), "+f"(c3)
        : "r"(a0), "r"(a1), "r"(a2), "r"(a3), "r"(b0), "r"(b1));
}

__device__ __forceinline__ void gemm_body(const float* __restrict__ A,
                                          const float* __restrict__ B,
                                          float* __restrict__ C,
                                          int M, int N, int K) {
    extern __shared__ float sm[];
    float* As = sm;
    float* Bs = sm + 2 * AS_ELEMS;

    const int tid  = threadIdx.x;
    const int warp = tid >> 5;
    const int lane = tid & 31;
    const int wm = warp & 3;
    const int wn = warp >> 2;
    const int g  = lane >> 2;
    const int tg = lane & 3;
    const int row0 = blockIdx.y * 128;
    const int col0 = blockIdx.x * 128;

    const int ar  = tid >> 3;
    const int akc = (tid & 7) << 2;
    const int br  = tid >> 5;
    const int bcc = (tid & 31) << 2;

    float c[2][8][4];
#pragma unroll
    for (int mi = 0; mi < 2; mi++)
#pragma unroll
        for (int ni = 0; ni < 8; ni++)
#pragma unroll
            for (int q = 0; q < 4; q++) c[mi][ni][q] = 0.0f;

    const int KT = K >> 5;

    auto fill = [&](int s, int kt) {
        float* as = As + s * AS_ELEMS;
        float* bs = Bs + s * BS_ELEMS;
#pragma unroll
        for (int it = 0; it < 4; it++) {
            int r = ar + it * 32;
            int sz = (row0 + r < M) ? 16 : 0;
            cp16(as + r * AS_STRIDE + akc,
                 A + (size_t)(row0 + r) * K + kt + akc, sz);
        }
#pragma unroll
        for (int it = 0; it < 4; it++) {
            int r = br + it * 8;
            cp16(bs + r * BS_STRIDE + bcc,
                 B + (size_t)(kt + r) * N + col0 + bcc, 16);
        }
    };

    fill(0, 0);
    cp_commit();

    for (int kti = 0; kti < KT; kti++) {
        if (kti + 1 < KT) fill((kti + 1) & 1, (kti + 1) * 32);
        cp_commit();
        cp_wait1();
        __syncthreads();

        const float* as = As + (kti & 1) * AS_ELEMS;
        const float* bs = Bs + (kti & 1) * BS_ELEMS;
#pragma unroll
        for (int ks = 0; ks < 4; ks++) {
            int k0 = ks * 8;
            unsigned a[2][4], b[8][2];
#pragma unroll
            for (int mi = 0; mi < 2; mi++) {
                int r = wm * 32 + mi * 16 + g;
                a[mi][0] = rna(as[r * AS_STRIDE + k0 + tg]);
                a[mi][1] = rna(as[(r + 8) * AS_STRIDE + k0 + tg]);
                a[mi][2] = rna(as[r * AS_STRIDE + k0 + tg + 4]);
                a[mi][3] = rna(as[(r + 8) * AS_STRIDE + k0 + tg + 4]);
            }
#pragma unroll
            for (int ni = 0; ni < 8; ni++) {
                int cc = wn * 64 + ni * 8 + g;
                b[ni][0] = rna(bs[(k0 + tg) * BS_STRIDE + cc]);
                b[ni][1] = rna(bs[(k0 + tg + 4) * BS_STRIDE + cc]);
            }
#pragma unroll
            for (int mi = 0; mi < 2; mi++)
#pragma unroll
                for (int ni = 0; ni < 8; ni++)
                    mma_tf32(c[mi][ni][0], c[mi][ni][1], c[mi][ni][2], c[mi][ni][3],
                             a[mi][0], a[mi][1], a[mi][2], a[mi][3],
                             b[ni][0], b[ni][1]);
        }
        __syncthreads();
    }

#pragma unroll
    for (int mi = 0; mi < 2; mi++) {
        int r0 = row0 + wm * 32 + mi * 16 + g;
#pragma unroll
        for (int ni = 0; ni < 8; ni++) {
            int cc = col0 + wn * 64 + ni * 8 + 2 * tg;
            if (r0 < M) {
                C[(size_t)r0 * N + cc]     = c[mi][ni][0];
                C[(size_t)r0 * N + cc + 1] = c[mi][ni][1];
            }
            if (r0 + 8 < M) {
                C[(size_t)(r0 + 8) * N + cc]     = c[mi][ni][2];
                C[(size_t)(r0 + 8) * N + cc + 1] = c[mi][ni][3];
            }
        }
    }
}

__global__ void k_gemm1(const float* __restrict__ X, const float* __restrict__ W) {
    gemm_body(X, W, g_H1, NN, H1F, INF);
}
__global__ void k_gemm2(const float* __restrict__ W) {
    gemm_body(g_A1, W, g_H2, NN, H2F, H1F);
}

// ---------------- fused CSR aggregate + self-loop + bias + leakyReLU ----------------
// one block per node, C threads (one channel each); no block-wide syncs,
// CSR index/coef loads are warp-uniform (L1 broadcast); unroll-4 for MLP.
template <int C>
__device__ __forceinline__ void agg_body(const float* __restrict__ H,
                                         const float* __restrict__ bias,
                                         float* __restrict__ Out) {
    const int n   = blockIdx.x;
    const int tid = threadIdx.x;
    const int beg = g_rowptr[n];
    const int end = g_rowptr[n + 1];

    float dv = g_dinv[n];
    float a0 = dv * dv * H[(size_t)n * C + tid];
    float a1 = 0.f, a2 = 0.f, a3 = 0.f;

    int j = beg;
    for (; j + 4 <= end; j += 4) {
        int s0 = __ldg(&g_csrc[j]);
        int s1 = __ldg(&g_csrc[j + 1]);
        int s2 = __ldg(&g_csrc[j + 2]);
        int s3 = __ldg(&g_csrc[j + 3]);
        float c0 = __ldg(&g_ccoef[j]);
        float c1 = __ldg(&g_ccoef[j + 1]);
        float c2 = __ldg(&g_ccoef[j + 2]);
        float c3 = __ldg(&g_ccoef[j + 3]);
        a0 += c0 * __ldg(&H[(size_t)s0 * C + tid]);
        a1 += c1 * __ldg(&H[(size_t)s1 * C + tid]);
        a2 += c2 * __ldg(&H[(size_t)s2 * C + tid]);
        a3 += c3 * __ldg(&H[(size_t)s3 * C + tid]);
    }
    for (; j < end; j++)
        a0 += __ldg(&g_ccoef[j]) * __ldg(&H[(size_t)__ldg(&g_csrc[j]) * C + tid]);

    float acc = (a0 + a1) + (a2 + a3) + bias[tid];
    acc = acc > 0.f ? acc : acc * NEG;
    Out[(size_t)n * C + tid] = acc;
}

__global__ void k_agg1(const float* __restrict__ b) { agg_body<H1F>(g_H1, b, g_A1); }
__global__ void k_agg2(const float* __restrict__ b, float* __restrict__ out) {
    agg_body<H2F>(g_H2, b, out);
}

// ---------------- launch (single stream; gemm1 hoisted to launch index 3) ----------------
extern "C" void kernel_launch(void* const* d_in, const int* in_sizes, int n_in,
                              void* d_out, int out_size) {
    const float* X  = (const float*)d_in[0];
    const int*   ew = (const int*)d_in[1];
    const float* W1 = (const float*)d_in[2];
    const float* b1 = (const float*)d_in[3];
    const float* W2 = (const float*)d_in[4];
    const float* b2 = (const float*)d_in[5];
    float* out = (float*)d_out;

    cudaFuncSetAttribute(k_gemm1, cudaFuncAttributeMaxDynamicSharedMemorySize, GEMM_SMEM);
    cudaFuncSetAttribute(k_gemm2, cudaFuncAttributeMaxDynamicSharedMemorySize, GEMM_SMEM);

    const int T = 256;
    k_zerodet<<<NBLK, T>>>(ew);                      // 0
    k_hist<<<(EE + T - 1) / T, T>>>(ew);             // 1
    k_scan1<<<NBLK, T>>>();                          // 2

    dim3 g1(H1F / 128, (NN + 127) / 128);
    k_gemm1<<<g1, 256, GEMM_SMEM>>>(X, W1);          // 3  <- ncu capture point

    k_scan23<<<NBLK, T>>>();                         // 4
    k_place<<<(EE + T - 1) / T, T>>>(ew);            // 5

    k_agg1<<<NN, H1F>>>(b1);                         // 6

    dim3 g2(H2F / 128, (NN + 127) / 128);
    k_gemm2<<<g2, 256, GEMM_SMEM>>>(W2);             // 7
    k_agg2<<<NN, H2F>>>(b2, out);                    // 8
}

// round 11
// speedup vs baseline: 3.3409x; 1.0038x over previous
#include <cuda_runtime.h>
#include <cuda_bf16.h>
#include <cstddef>

#define NN   50000
#define EE   800000
#define INF  512
#define H1F  256
#define H2F  128
#define NEG  0.2f
#define NBLK 196   // ceil(NN/256)

// ---------------- scratch (device globals) ----------------
__device__ int   g_is64;
__device__ int   g_cnt[NN];
__device__ int   g_cur[NN];
__device__ int   g_rowptr[NN + 1];
__device__ int   g_bsum[NBLK];
__device__ float g_dinv[NN];
__device__ int   g_csrc[EE];
__device__ float g_ccoef[EE];
__device__ float g_H1[NN * H1F];
__device__ float g_A1[NN * H1F];
__device__ float g_H2[NN * H2F];

// ---------------- zero + edge dtype detect (merged) ----------------
__global__ void k_zerodet(const int* __restrict__ w) {
    int i = blockIdx.x * blockDim.x + threadIdx.x;
    if (i < NN) { g_cnt[i] = 0; g_cur[i] = 0; }
    if (blockIdx.x == 0) {
        __shared__ int nz;
        if (threadIdx.x == 0) nz = 0;
        __syncthreads();
        for (int j = threadIdx.x; j < 1024; j += blockDim.x)
            if (w[2 * j + 1] != 0) atomicOr(&nz, 1);
        __syncthreads();
        if (threadIdx.x == 0) g_is64 = (nz == 0) ? 1 : 0;
    }
}

// histogram of dst (reads edge words directly)
__global__ void k_hist(const int* __restrict__ w) {
    int e = blockIdx.x * blockDim.x + threadIdx.x;
    if (e >= EE) return;
    int d = g_is64 ? w[2 * EE + 2 * e] : w[EE + e];
    atomicAdd(&g_cnt[d], 1);
}

__global__ void k_scan1() {
    __shared__ int sh[256];
    int tid = threadIdx.x;
    int i = blockIdx.x * 256 + tid;
    sh[tid] = (i < NN) ? g_cnt[i] : 0;
    __syncthreads();
    for (int ofs = 128; ofs > 0; ofs >>= 1) {
        if (tid < ofs) sh[tid] += sh[tid + ofs];
        __syncthreads();
    }
    if (tid == 0) g_bsum[blockIdx.x] = sh[0];
}

__global__ void k_scan23() {
    __shared__ int sh[256];
    __shared__ int boff_sh;
    int tid = threadIdx.x;
    int b = blockIdx.x;
    sh[tid] = (tid < b) ? g_bsum[tid] : 0;
    __syncthreads();
    for (int ofs = 128; ofs > 0; ofs >>= 1) {
        if (tid < ofs) sh[tid] += sh[tid + ofs];
        __syncthreads();
    }
    if (tid == 0) boff_sh = sh[0];
    __syncthreads();
    int boff = boff_sh;
    __syncthreads();
    int i = b * 256 + tid;
    int v = (i < NN) ? g_cnt[i] : 0;
    sh[tid] = v;
    __syncthreads();
    for (int ofs = 1; ofs < 256; ofs <<= 1) {
        int t = (tid >= ofs) ? sh[tid - ofs] : 0;
        __syncthreads();
        sh[tid] += t;
        __syncthreads();
    }
    if (i < NN) {
        g_rowptr[i] = sh[tid] - v + boff;
        g_dinv[i] = rsqrtf((float)v + 1.0f);
    }
    if (b == 0 && tid == 0) g_rowptr[NN] = EE;
}

__global__ void k_place(const int* __restrict__ w) {
    int e = blockIdx.x * blockDim.x + threadIdx.x;
    if (e >= EE) return;
    int s, d;
    if (g_is64) { s = w[2 * e]; d = w[2 * EE + 2 * e]; }
    else        { s = w[e];     d = w[EE + e]; }
    float cf = g_dinv[s] * g_dinv[d];
    int pos = g_rowptr[d] + atomicAdd(&g_cur[d], 1);
    g_csrc[pos]  = s;
    g_ccoef[pos] = cf;
}

// ---------------- TF32 tensor-core GEMM, cp.async 2-stage, 128x128 tile ----------------
#define AS_STRIDE 36
#define BS_STRIDE 136
#define AS_ELEMS  (128 * AS_STRIDE)
#define BS_ELEMS  (32 * BS_STRIDE)
#define GEMM_SMEM ((2 * (AS_ELEMS + BS_ELEMS)) * 4)   // 71680 B

__device__ __forceinline__ void cp16(void* dst_smem, const void* src, int sz) {
    unsigned d = (unsigned)__cvta_generic_to_shared(dst_smem);
    asm volatile("cp.async.cg.shared.global [%0], [%1], 16, %2;\n"
                 :: "r"(d), "l"(src), "r"(sz));
}
__device__ __forceinline__ void cp_commit() {
    asm volatile("cp.async.commit_group;\n");
}
__device__ __forceinline__ void cp_wait1() {
    asm volatile("cp.async.wait_group 1;\n");
}
__device__ __forceinline__ unsigned rna(float x) {
    unsigned r;
    asm("cvt.rna.tf32.f32 %0, %1;" : "=r"(r) : "f"(x));
    return r;
}

__device__ __forceinline__ void mma_tf32(float& c0, float& c1, float& c2, float& c3,
                                         unsigned a0, unsigned a1, unsigned a2, unsigned a3,
                                         unsigned b0, unsigned b1) {
    asm volatile(
        "mma.sync.aligned.m16n8k8.row.col.f32.tf32.tf32.f32 "
        "{%0,%1,%2,%3},{%4,%5,%6,%7},{%8,%9},{%0,%1,%2,%3};"
        : "+f"(c0), "+f"(c1), "+f"(c2), "+f"(c3)
        : "r"(a0), "r"(a1), "r"(a2), "r"(a3), "r"(b0), "r"(b1));
}

__device__ __forceinline__ void gemm_body(const float* __restrict__ A,
                                          const float* __restrict__ B,
                                          float* __restrict__ C,
                                          int M, int N, int K) {
    extern __shared__ float sm[];
    float* As = sm;
    float* Bs = sm + 2 * AS_ELEMS;

    const int tid  = threadIdx.x;
    const int warp = tid >> 5;
    const int lane = tid & 31;
    const int wm = warp & 3;
    const int wn = warp >> 2;
    const int g  = lane >> 2;
    const int tg = lane & 3;
    const int row0 = blockIdx.y * 128;
    const int col0 = blockIdx.x * 128;

    const int ar  = tid >> 3;
    const int akc = (tid & 7) << 2;
    const int br  = tid >> 5;
    const int bcc = (tid & 31) << 2;

    float c[2][8][4];
#pragma unroll
    for (int mi = 0; mi < 2; mi++)
#pragma unroll
        for (int ni = 0; ni < 8; ni++)
#pragma unroll
            for (int q = 0; q < 4; q++) c[mi][ni][q] = 0.0f;

    const int KT = K >> 5;

    auto fill = [&](int s, int kt) {
        float* as = As + s * AS_ELEMS;
        float* bs = Bs + s * BS_ELEMS;
#pragma unroll
        for (int it = 0; it < 4; it++) {
            int r = ar + it * 32;
            int sz = (row0 + r < M) ? 16 : 0;
            cp16(as + r * AS_STRIDE + akc,
                 A + (size_t)(row0 + r) * K + kt + akc, sz);
        }
#pragma unroll
        for (int it = 0; it < 4; it++) {
            int r = br + it * 8;
            cp16(bs + r * BS_STRIDE + bcc,
                 B + (size_t)(kt + r) * N + col0 + bcc, 16);
        }
    };

    fill(0, 0);
    cp_commit();

    for (int kti = 0; kti < KT; kti++) {
        if (kti + 1 < KT) fill((kti + 1) & 1, (kti + 1) * 32);
        cp_commit();
        cp_wait1();
        __syncthreads();

        const float* as = As + (kti & 1) * AS_ELEMS;
        const float* bs = Bs + (kti & 1) * BS_ELEMS;
#pragma unroll
        for (int ks = 0; ks < 4; ks++) {
            int k0 = ks * 8;
            unsigned a[2][4], b[8][2];
#pragma unroll
            for (int mi = 0; mi < 2; mi++) {
                int r = wm * 32 + mi * 16 + g;
                a[mi][0] = rna(as[r * AS_STRIDE + k0 + tg]);
                a[mi][1] = rna(as[(r + 8) * AS_STRIDE + k0 + tg]);
                a[mi][2] = rna(as[r * AS_STRIDE + k0 + tg + 4]);
                a[mi][3] = rna(as[(r + 8) * AS_STRIDE + k0 + tg + 4]);
            }
#pragma unroll
            for (int ni = 0; ni < 8; ni++) {
                int cc = wn * 64 + ni * 8 + g;
                b[ni][0] = rna(bs[(k0 + tg) * BS_STRIDE + cc]);
                b[ni][1] = rna(bs[(k0 + tg + 4) * BS_STRIDE + cc]);
            }
#pragma unroll
            for (int mi = 0; mi < 2; mi++)
#pragma unroll
                for (int ni = 0; ni < 8; ni++)
                    mma_tf32(c[mi][ni][0], c[mi][ni][1], c[mi][ni][2], c[mi][ni][3],
                             a[mi][0], a[mi][1], a[mi][2], a[mi][3],
                             b[ni][0], b[ni][1]);
        }
        __syncthreads();
    }

#pragma unroll
    for (int mi = 0; mi < 2; mi++) {
        int r0 = row0 + wm * 32 + mi * 16 + g;
#pragma unroll
        for (int ni = 0; ni < 8; ni++) {
            int cc = col0 + wn * 64 + ni * 8 + 2 * tg;
            if (r0 < M) {
                C[(size_t)r0 * N + cc]     = c[mi][ni][0];
                C[(size_t)r0 * N + cc + 1] = c[mi][ni][1];
            }
            if (r0 + 8 < M) {
                C[(size_t)(r0 + 8) * N + cc]     = c[mi][ni][2];
                C[(size_t)(r0 + 8) * N + cc + 1] = c[mi][ni][3];
            }
        }
    }
}

__global__ void k_gemm1(const float* __restrict__ X, const float* __restrict__ W) {
    gemm_body(X, W, g_H1, NN, H1F, INF);
}
__global__ void k_gemm2(const float* __restrict__ W) {
    gemm_body(g_A1, W, g_H2, NN, H2F, H1F);
}

// ---------------- fused CSR aggregate + self-loop + bias + leakyReLU ----------------
// one block per node, C threads (one channel each); no block-wide syncs,
// CSR index/coef loads are warp-uniform (L1 broadcast); unroll-4 for MLP.
template <int C>
__device__ __forceinline__ void agg_body(const float* __restrict__ H,
                                         const float* __restrict__ bias,
                                         float* __restrict__ Out) {
    const int n   = blockIdx.x;
    const int tid = threadIdx.x;
    const int beg = g_rowptr[n];
    const int end = g_rowptr[n + 1];

    float dv = g_dinv[n];
    float a0 = dv * dv * H[(size_t)n * C + tid];
    float a1 = 0.f, a2 = 0.f, a3 = 0.f;

    int j = beg;
    for (; j + 4 <= end; j += 4) {
        int s0 = __ldg(&g_csrc[j]);
        int s1 = __ldg(&g_csrc[j + 1]);
        int s2 = __ldg(&g_csrc[j + 2]);
        int s3 = __ldg(&g_csrc[j + 3]);
        float c0 = __ldg(&g_ccoef[j]);
        float c1 = __ldg(&g_ccoef[j + 1]);
        float c2 = __ldg(&g_ccoef[j + 2]);
        float c3 = __ldg(&g_ccoef[j + 3]);
        a0 += c0 * __ldg(&H[(size_t)s0 * C + tid]);
        a1 += c1 * __ldg(&H[(size_t)s1 * C + tid]);
        a2 += c2 * __ldg(&H[(size_t)s2 * C + tid]);
        a3 += c3 * __ldg(&H[(size_t)s3 * C + tid]);
    }
    for (; j < end; j++)
        a0 += __ldg(&g_ccoef[j]) * __ldg(&H[(size_t)__ldg(&g_csrc[j]) * C + tid]);

    float acc = (a0 + a1) + (a2 + a3) + bias[tid];
    acc = acc > 0.f ? acc : acc * NEG;
    Out[(size_t)n * C + tid] = acc;
}

__global__ void k_agg1(const float* __restrict__ b) { agg_body<H1F>(g_H1, b, g_A1); }
__global__ void k_agg2(const float* __restrict__ b, float* __restrict__ out) {
    agg_body<H2F>(g_H2, b, out);
}

// ---------------- launch (single stream; gemm1 hoisted to launch index 3) ----------------
extern "C" void kernel_launch(void* const* d_in, const int* in_sizes, int n_in,
                              void* d_out, int out_size) {
    const float* X  = (const float*)d_in[0];
    const int*   ew = (const int*)d_in[1];
    const float* W1 = (const float*)d_in[2];
    const float* b1 = (const float*)d_in[3];
    const float* W2 = (const float*)d_in[4];
    const float* b2 = (const float*)d_in[5];
    float* out = (float*)d_out;

    cudaFuncSetAttribute(k_gemm1, cudaFuncAttributeMaxDynamicSharedMemorySize, GEMM_SMEM);
    cudaFuncSetAttribute(k_gemm2, cudaFuncAttributeMaxDynamicSharedMemorySize, GEMM_SMEM);

    const int T = 256;
    k_zerodet<<<NBLK, T>>>(ew);                      // 0
    k_hist<<<(EE + T - 1) / T, T>>>(ew);             // 1
    k_scan1<<<NBLK, T>>>();                          // 2

    dim3 g1(H1F / 128, (NN + 127) / 128);
    k_gemm1<<<g1, 256, GEMM_SMEM>>>(X, W1);          // 3  <- ncu capture point

    k_scan23<<<NBLK, T>>>();                         // 4
    k_place<<<(EE + T - 1) / T, T>>>(ew);            // 5

    k_agg1<<<NN, H1F>>>(b1);                         // 6

    dim3 g2(H2F / 128, (NN + 127) / 128);
    k_gemm2<<<g2, 256, GEMM_SMEM>>>(W2);             // 7
    k_agg2<<<NN, H2F>>>(b2, out);                    // 8
}

// round 12
// speedup vs baseline: 3.4115x; 1.0211x over previous
#include <cuda_runtime.h>
#include <cuda_bf16.h>
#include <cstddef>

#define NN   50000
#define EE   800000
#define INF  512
#define H1F  256
#define H2F  128
#define NEG  0.2f
#define NBLK 196   // ceil(NN/256)

// ---------------- scratch (device globals) ----------------
__device__ int   g_is64;
__device__ int   g_cnt[NN];
__device__ int   g_cur[NN];
__device__ int   g_rowptr[NN + 1];
__device__ int   g_bsum[NBLK];
__device__ float g_dinv[NN];
__device__ int   g_csrc[EE];
__device__ float g_ccoef[EE];
__device__ float g_W1T[H1F * INF];   // W1^T, tf32-rounded, [N][K]
__device__ float g_W2T[H2F * H1F];   // W2^T, tf32-rounded, [N][K]
__device__ float g_H1[NN * H1F];
__device__ float g_A1[NN * H1F];     // tf32-rounded activations
__device__ float g_H2[NN * H2F];

__device__ __forceinline__ unsigned rna(float x) {
    unsigned r;
    asm("cvt.rna.tf32.f32 %0, %1;" : "=r"(r) : "f"(x));
    return r;
}

// ---------------- zero + edge dtype detect (merged) ----------------
__global__ void k_zerodet(const int* __restrict__ w) {
    int i = blockIdx.x * blockDim.x + threadIdx.x;
    if (i < NN) { g_cnt[i] = 0; g_cur[i] = 0; }
    if (blockIdx.x == 0) {
        __shared__ int nz;
        if (threadIdx.x == 0) nz = 0;
        __syncthreads();
        for (int j = threadIdx.x; j < 1024; j += blockDim.x)
            if (w[2 * j + 1] != 0) atomicOr(&nz, 1);
        __syncthreads();
        if (threadIdx.x == 0) g_is64 = (nz == 0) ? 1 : 0;
    }
}

__global__ void k_hist(const int* __restrict__ w) {
    int e = blockIdx.x * blockDim.x + threadIdx.x;
    if (e >= EE) return;
    int d = g_is64 ? w[2 * EE + 2 * e] : w[EE + e];
    atomicAdd(&g_cnt[d], 1);
}

// transpose + tf32-round both weight matrices (tiny)
__global__ void k_wt(const float* __restrict__ W1, const float* __restrict__ W2) {
    int i = blockIdx.x * blockDim.x + threadIdx.x;
    if (i < INF * H1F) {
        int n = i / INF, k = i % INF;
        g_W1T[i] = __uint_as_float(rna(W1[(size_t)k * H1F + n]));
    }
    if (i < H1F * H2F) {
        int n = i / H1F, k = i % H1F;
        g_W2T[i] = __uint_as_float(rna(W2[(size_t)k * H2F + n]));
    }
}

__global__ void k_scan1() {
    __shared__ int sh[256];
    int tid = threadIdx.x;
    int i = blockIdx.x * 256 + tid;
    sh[tid] = (i < NN) ? g_cnt[i] : 0;
    __syncthreads();
    for (int ofs = 128; ofs > 0; ofs >>= 1) {
        if (tid < ofs) sh[tid] += sh[tid + ofs];
        __syncthreads();
    }
    if (tid == 0) g_bsum[blockIdx.x] = sh[0];
}

__global__ void k_scan23() {
    __shared__ int sh[256];
    __shared__ int boff_sh;
    int tid = threadIdx.x;
    int b = blockIdx.x;
    sh[tid] = (tid < b) ? g_bsum[tid] : 0;
    __syncthreads();
    for (int ofs = 128; ofs > 0; ofs >>= 1) {
        if (tid < ofs) sh[tid] += sh[tid + ofs];
        __syncthreads();
    }
    if (tid == 0) boff_sh = sh[0];
    __syncthreads();
    int boff = boff_sh;
    __syncthreads();
    int i = b * 256 + tid;
    int v = (i < NN) ? g_cnt[i] : 0;
    sh[tid] = v;
    __syncthreads();
    for (int ofs = 1; ofs < 256; ofs <<= 1) {
        int t = (tid >= ofs) ? sh[tid - ofs] : 0;
        __syncthreads();
        sh[tid] += t;
        __syncthreads();
    }
    if (i < NN) {
        g_rowptr[i] = sh[tid] - v + boff;
        g_dinv[i] = rsqrtf((float)v + 1.0f);
    }
    if (b == 0 && tid == 0) g_rowptr[NN] = EE;
}

__global__ void k_place(const int* __restrict__ w) {
    int e = blockIdx.x * blockDim.x + threadIdx.x;
    if (e >= EE) return;
    int s, d;
    if (g_is64) { s = w[2 * e]; d = w[2 * EE + 2 * e]; }
    else        { s = w[e];     d = w[EE + e]; }
    float cf = g_dinv[s] * g_dinv[d];
    int pos = g_rowptr[d] + atomicAdd(&g_cur[d], 1);
    g_csrc[pos]  = s;
    g_ccoef[pos] = cf;
}

// ---------------- TF32 GEMM, cp.async 2-stage, 128x128 tile, ldmatrix frags ----------------
// A: [M][K] k-major (fp32 or pre-rounded). B: WT [N][K] k-major, pre-rounded tf32.
#define TS 36                       // smem row stride in floats (32 + 4 pad)
#define TILE_ELEMS (128 * TS)       // 4608 per operand per stage
#define GEMM_SMEM (4 * TILE_ELEMS * 4)   // 2 stages x 2 operands = 73728 B

__device__ __forceinline__ void cp16(void* dst_smem, const void* src, int sz) {
    unsigned d = (unsigned)__cvta_generic_to_shared(dst_smem);
    asm volatile("cp.async.cg.shared.global [%0], [%1], 16, %2;\n"
                 :: "r"(d), "l"(src), "r"(sz));
}
__device__ __forceinline__ void cp_commit() {
    asm volatile("cp.async.commit_group;\n");
}
__device__ __forceinline__ void cp_wait1() {
    asm volatile("cp.async.wait_group 1;\n");
}
__device__ __forceinline__ void ldsm4(unsigned& r0, unsigned& r1, unsigned& r2, unsigned& r3,
                                      const float* p) {
    unsigned a = (unsigned)__cvta_generic_to_shared(p);
    asm volatile("ldmatrix.sync.aligned.m8n8.x4.shared.b16 {%0,%1,%2,%3}, [%4];"
                 : "=r"(r0), "=r"(r1), "=r"(r2), "=r"(r3) : "r"(a));
}

__device__ __forceinline__ void mma_tf32(float& c0, float& c1, float& c2, float& c3,
                                         unsigned a0, unsigned a1, unsigned a2, unsigned a3,
                                         unsigned b0, unsigned b1) {
    asm volatile(
        "mma.sync.aligned.m16n8k8.row.col.f32.tf32.tf32.f32 "
        "{%0,%1,%2,%3},{%4,%5,%6,%7},{%8,%9},{%0,%1,%2,%3};"
        : "+f"(c0), "+f"(c1), "+f"(c2), "+f"(c3)
        : "r"(a0), "r"(a1), "r"(a2), "r"(a3), "r"(b0), "r"(b1));
}

template <bool CVT_A>
__device__ __forceinline__ void gemm_body(const float* __restrict__ A,
                                          const float* __restrict__ WT,
                                          float* __restrict__ C,
                                          int M, int N, int K) {
    extern __shared__ float sm[];
    float* As = sm;                       // [2][128][TS]
    float* Bs = sm + 2 * TILE_ELEMS;      // [2][128][TS] (n-major)

    const int tid  = threadIdx.x;
    const int warp = tid >> 5;
    const int lane = tid & 31;
    const int wm = warp & 3;    // M offset 32*wm
    const int wn = warp >> 2;   // N offset 64*wn
    const int g  = lane >> 2;
    const int tg = lane & 3;
    const int row0 = blockIdx.y * 128;
    const int col0 = blockIdx.x * 128;

    // cp.async fill indices (same pattern both operands: 128 rows x 32 floats)
    const int fr  = tid >> 3;           // 0..31 (row within 32-row slab)
    const int fc  = (tid & 7) << 2;     // float col 0,4,..,28

    // ldmatrix per-lane fragment offsets (in floats, k0 added per step)
    int aoff[2], boff[4];
#pragma unroll
    for (int mi = 0; mi < 2; mi++) {
        int r = wm * 32 + mi * 16 + ((lane >> 3) & 1) * 8 + (lane & 7);
        aoff[mi] = r * TS + (lane >> 4) * 4;
    }
#pragma unroll
    for (int p = 0; p < 4; p++) {
        int r = wn * 64 + p * 16 + ((lane >> 4) & 1) * 8 + (lane & 7);
        boff[p] = r * TS + ((lane >> 3) & 1) * 4;
    }

    float c[2][8][4];
#pragma unroll
    for (int mi = 0; mi < 2; mi++)
#pragma unroll
        for (int ni = 0; ni < 8; ni++)
#pragma unroll
            for (int q = 0; q < 4; q++) c[mi][ni][q] = 0.0f;

    const int KT = K >> 5;

    auto fill = [&](int s, int kt) {
        float* as = As + s * TILE_ELEMS;
        float* bs = Bs + s * TILE_ELEMS;
#pragma unroll
        for (int it = 0; it < 4; it++) {
            int r = fr + it * 32;
            int sz = (row0 + r < M) ? 16 : 0;
            cp16(as + r * TS + fc, A + (size_t)(row0 + r) * K + kt + fc, sz);
        }
#pragma unroll
        for (int it = 0; it < 4; it++) {
            int r = fr + it * 32;
            cp16(bs + r * TS + fc, WT + (size_t)(col0 + r) * K + kt + fc, 16);
        }
    };

    fill(0, 0);
    cp_commit();

    for (int kti = 0; kti < KT; kti++) {
        if (kti + 1 < KT) fill((kti + 1) & 1, (kti + 1) * 32);
        cp_commit();
        cp_wait1();
        __syncthreads();

        const float* as = As + (kti & 1) * TILE_ELEMS;
        const float* bs = Bs + (kti & 1) * TILE_ELEMS;
#pragma unroll
        for (int ks = 0; ks < 4; ks++) {
            int k0 = ks * 8;
            unsigned a[2][4], b[8][2];
#pragma unroll
            for (int mi = 0; mi < 2; mi++) {
                ldsm4(a[mi][0], a[mi][1], a[mi][2], a[mi][3], as + aoff[mi] + k0);
                if (CVT_A) {
#pragma unroll
                    for (int q = 0; q < 4; q++)
                        a[mi][q] = rna(__uint_as_float(a[mi][q]));
                }
            }
#pragma unroll
            for (int p = 0; p < 4; p++)
                ldsm4(b[2 * p][0], b[2 * p][1], b[2 * p + 1][0], b[2 * p + 1][1],
                      bs + boff[p] + k0);
#pragma unroll
            for (int mi = 0; mi < 2; mi++)
#pragma unroll
                for (int ni = 0; ni < 8; ni++)
                    mma_tf32(c[mi][ni][0], c[mi][ni][1], c[mi][ni][2], c[mi][ni][3],
                             a[mi][0], a[mi][1], a[mi][2], a[mi][3],
                             b[ni][0], b[ni][1]);
        }
        __syncthreads();
    }

#pragma unroll
    for (int mi = 0; mi < 2; mi++) {
        int r0 = row0 + wm * 32 + mi * 16 + g;
#pragma unroll
        for (int ni = 0; ni < 8; ni++) {
            int cc = col0 + wn * 64 + ni * 8 + 2 * tg;
            if (r0 < M) {
                C[(size_t)r0 * N + cc]     = c[mi][ni][0];
                C[(size_t)r0 * N + cc + 1] = c[mi][ni][1];
            }
            if (r0 + 8 < M) {
                C[(size_t)(r0 + 8) * N + cc]     = c[mi][ni][2];
                C[(size_t)(r0 + 8) * N + cc + 1] = c[mi][ni][3];
            }
        }
    }
}

__global__ void k_gemm1(const float* __restrict__ X) {
    gemm_body<true>(X, g_W1T, g_H1, NN, H1F, INF);
}
__global__ void k_gemm2() {
    gemm_body<false>(g_A1, g_W2T, g_H2, NN, H2F, H1F);
}

// ---------------- fused CSR aggregate + self-loop + bias + leakyReLU ----------------
// ROUND: store tf32-rounded output (feeds next GEMM's A with no CVT needed)
template <int C, bool ROUND>
__device__ __forceinline__ void agg_body(const float* __restrict__ H,
                                         const float* __restrict__ bias,
                                         float* __restrict__ Out) {
    const int n   = blockIdx.x;
    const int tid = threadIdx.x;
    const int beg = g_rowptr[n];
    const int end = g_rowptr[n + 1];

    float dv = g_dinv[n];
    float a0 = dv * dv * H[(size_t)n * C + tid];
    float a1 = 0.f, a2 = 0.f, a3 = 0.f;

    int j = beg;
    for (; j + 4 <= end; j += 4) {
        int s0 = __ldg(&g_csrc[j]);
        int s1 = __ldg(&g_csrc[j + 1]);
        int s2 = __ldg(&g_csrc[j + 2]);
        int s3 = __ldg(&g_csrc[j + 3]);
        float c0 = __ldg(&g_ccoef[j]);
        float c1 = __ldg(&g_ccoef[j + 1]);
        float c2 = __ldg(&g_ccoef[j + 2]);
        float c3 = __ldg(&g_ccoef[j + 3]);
        a0 += c0 * __ldg(&H[(size_t)s0 * C + tid]);
        a1 += c1 * __ldg(&H[(size_t)s1 * C + tid]);
        a2 += c2 * __ldg(&H[(size_t)s2 * C + tid]);
        a3 += c3 * __ldg(&H[(size_t)s3 * C + tid]);
    }
    for (; j < end; j++)
        a0 += __ldg(&g_ccoef[j]) * __ldg(&H[(size_t)__ldg(&g_csrc[j]) * C + tid]);

    float acc = (a0 + a1) + (a2 + a3) + bias[tid];
    acc = acc > 0.f ? acc : acc * NEG;
    if (ROUND) acc = __uint_as_float(rna(acc));
    Out[(size_t)n * C + tid] = acc;
}

__global__ void k_agg1(const float* __restrict__ b) { agg_body<H1F, true>(g_H1, b, g_A1); }
__global__ void k_agg2(const float* __restrict__ b, float* __restrict__ out) {
    agg_body<H2F, false>(g_H2, b, out);
}

// ---------------- launch (single stream; gemm1 at launch index 3 for ncu) ----------------
extern "C" void kernel_launch(void* const* d_in, const int* in_sizes, int n_in,
                              void* d_out, int out_size) {
    const float* X  = (const float*)d_in[0];
    const int*   ew = (const int*)d_in[1];
    const float* W1 = (const float*)d_in[2];
    const float* b1 = (const float*)d_in[3];
    const float* W2 = (const float*)d_in[4];
    const float* b2 = (const float*)d_in[5];
    float* out = (float*)d_out;

    cudaFuncSetAttribute(k_gemm1, cudaFuncAttributeMaxDynamicSharedMemorySize, GEMM_SMEM);
    cudaFuncSetAttribute(k_gemm2, cudaFuncAttributeMaxDynamicSharedMemorySize, GEMM_SMEM);

    const int T = 256;
    k_zerodet<<<NBLK, T>>>(ew);                      // 0
    k_hist<<<(EE + T - 1) / T, T>>>(ew);             // 1
    k_wt<<<(INF * H1F + T - 1) / T, T>>>(W1, W2);    // 2

    dim3 g1(H1F / 128, (NN + 127) / 128);
    k_gemm1<<<g1, 256, GEMM_SMEM>>>(X);              // 3  <- ncu capture point

    k_scan1<<<NBLK, T>>>();                          // 4
    k_scan23<<<NBLK, T>>>();                         // 5
    k_place<<<(EE + T - 1) / T, T>>>(ew);            // 6

    k_agg1<<<NN, H1F>>>(b1);                         // 7

    dim3 g2(H2F / 128, (NN + 127) / 128);
    k_gemm2<<<g2, 256, GEMM_SMEM>>>();               // 8
    k_agg2<<<NN, H2F>>>(b2, out);                    // 9
}

// round 13
// speedup vs baseline: 4.8708x; 1.4278x over previous
#include <cuda_runtime.h>
#include <cuda_bf16.h>
#include <cstddef>

#define NN   50000
#define EE   800000
#define INF  512
#define H1F  256
#define H2F  128
#define NEG  0.2f
#define NBLK 196   // ceil(NN/256)

// ---------------- scratch (device globals) ----------------
__device__ int   g_is64;
__device__ int   g_cnt[NN];
__device__ int   g_cur[NN];
__device__ int   g_rowptr[NN + 1];
__device__ int   g_bsum[NBLK];
__device__ float g_dinv[NN];
__device__ int   g_csrc[EE];
__device__ float g_ccoef[EE];
__device__ float g_W1T[H1F * INF];   // W1^T, tf32-rounded, [N][K]
__device__ float g_W2T[H2F * H1F];   // W2^T, tf32-rounded, [N][K]
__device__ float g_H1[NN * H1F];
__device__ float g_A1[NN * H1F];     // tf32-rounded activations
__device__ float g_H2[NN * H2F];

__device__ __forceinline__ unsigned rna(float x) {
    unsigned r;
    asm("cvt.rna.tf32.f32 %0, %1;" : "=r"(r) : "f"(x));
    return r;
}

// ---------------- zero + edge dtype detect (merged) ----------------
__global__ void k_zerodet(const int* __restrict__ w) {
    int i = blockIdx.x * blockDim.x + threadIdx.x;
    if (i < NN) { g_cnt[i] = 0; g_cur[i] = 0; }
    if (blockIdx.x == 0) {
        __shared__ int nz;
        if (threadIdx.x == 0) nz = 0;
        __syncthreads();
        for (int j = threadIdx.x; j < 1024; j += blockDim.x)
            if (w[2 * j + 1] != 0) atomicOr(&nz, 1);
        __syncthreads();
        if (threadIdx.x == 0) g_is64 = (nz == 0) ? 1 : 0;
    }
}

__global__ void k_hist(const int* __restrict__ w) {
    int e = blockIdx.x * blockDim.x + threadIdx.x;
    if (e >= EE) return;
    int d = g_is64 ? w[2 * EE + 2 * e] : w[EE + e];
    atomicAdd(&g_cnt[d], 1);
}

// transpose + tf32-round both weight matrices (tiny)
__global__ void k_wt(const float* __restrict__ W1, const float* __restrict__ W2) {
    int i = blockIdx.x * blockDim.x + threadIdx.x;
    if (i < INF * H1F) {
        int n = i / INF, k = i % INF;
        g_W1T[i] = __uint_as_float(rna(W1[(size_t)k * H1F + n]));
    }
    if (i < H1F * H2F) {
        int n = i / H1F, k = i % H1F;
        g_W2T[i] = __uint_as_float(rna(W2[(size_t)k * H2F + n]));
    }
}

__global__ void k_scan1() {
    __shared__ int sh[256];
    int tid = threadIdx.x;
    int i = blockIdx.x * 256 + tid;
    sh[tid] = (i < NN) ? g_cnt[i] : 0;
    __syncthreads();
    for (int ofs = 128; ofs > 0; ofs >>= 1) {
        if (tid < ofs) sh[tid] += sh[tid + ofs];
        __syncthreads();
    }
    if (tid == 0) g_bsum[blockIdx.x] = sh[0];
}

__global__ void k_scan23() {
    __shared__ int sh[256];
    __shared__ int boff_sh;
    int tid = threadIdx.x;
    int b = blockIdx.x;
    sh[tid] = (tid < b) ? g_bsum[tid] : 0;
    __syncthreads();
    for (int ofs = 128; ofs > 0; ofs >>= 1) {
        if (tid < ofs) sh[tid] += sh[tid + ofs];
        __syncthreads();
    }
    if (tid == 0) boff_sh = sh[0];
    __syncthreads();
    int boff = boff_sh;
    __syncthreads();
    int i = b * 256 + tid;
    int v = (i < NN) ? g_cnt[i] : 0;
    sh[tid] = v;
    __syncthreads();
    for (int ofs = 1; ofs < 256; ofs <<= 1) {
        int t = (tid >= ofs) ? sh[tid - ofs] : 0;
        __syncthreads();
        sh[tid] += t;
        __syncthreads();
    }
    if (i < NN) {
        g_rowptr[i] = sh[tid] - v + boff;
        g_dinv[i] = rsqrtf((float)v + 1.0f);
    }
    if (b == 0 && tid == 0) g_rowptr[NN] = EE;
}

__global__ void k_place(const int* __restrict__ w) {
    int e = blockIdx.x * blockDim.x + threadIdx.x;
    if (e >= EE) return;
    int s, d;
    if (g_is64) { s = w[2 * e]; d = w[2 * EE + 2 * e]; }
    else        { s = w[e];     d = w[EE + e]; }
    float cf = g_dinv[s] * g_dinv[d];
    int pos = g_rowptr[d] + atomicAdd(&g_cur[d], 1);
    g_csrc[pos]  = s;
    g_ccoef[pos] = cf;
}

// ---------------- TF32 GEMM: 3-stage cp.async, 128x128 tile, XOR-swizzled smem ----------------
// A: [M][K] k-major. B: WT [N][K] k-major pre-rounded tf32.
// smem row = 32 floats = 8 granules of 16B; granule index g ^= (row & 7).
#define TILE_ELEMS (128 * 32)                 // 4096 floats per operand per stage
#define NSTAGE 3
#define GEMM_SMEM (NSTAGE * 2 * TILE_ELEMS * 4)   // 98304 B

__device__ __forceinline__ void cp16(void* dst_smem, const void* src, int sz) {
    unsigned d = (unsigned)__cvta_generic_to_shared(dst_smem);
    asm volatile("cp.async.cg.shared.global [%0], [%1], 16, %2;\n"
                 :: "r"(d), "l"(src), "r"(sz));
}
__device__ __forceinline__ void cp_commit() {
    asm volatile("cp.async.commit_group;\n");
}
__device__ __forceinline__ void cp_wait1() {
    asm volatile("cp.async.wait_group 1;\n");
}
__device__ __forceinline__ void ldsm4(unsigned& r0, unsigned& r1, unsigned& r2, unsigned& r3,
                                      const float* p) {
    unsigned a = (unsigned)__cvta_generic_to_shared(p);
    asm volatile("ldmatrix.sync.aligned.m8n8.x4.shared.b16 {%0,%1,%2,%3}, [%4];"
                 : "=r"(r0), "=r"(r1), "=r"(r2), "=r"(r3) : "r"(a));
}

__device__ __forceinline__ void mma_tf32(float& c0, float& c1, float& c2, float& c3,
                                         unsigned a0, unsigned a1, unsigned a2, unsigned a3,
                                         unsigned b0, unsigned b1) {
    asm volatile(
        "mma.sync.aligned.m16n8k8.row.col.f32.tf32.tf32.f32 "
        "{%0,%1,%2,%3},{%4,%5,%6,%7},{%8,%9},{%0,%1,%2,%3};"
        : "+f"(c0), "+f"(c1), "+f"(c2), "+f"(c3)
        : "r"(a0), "r"(a1), "r"(a2), "r"(a3), "r"(b0), "r"(b1));
}

template <bool CVT_A>
__device__ __forceinline__ void gemm_body(const float* __restrict__ A,
                                          const float* __restrict__ WT,
                                          float* __restrict__ C,
                                          int M, int N, int K) {
    extern __shared__ float sm[];
    float* As = sm;                               // [NSTAGE][128][32] swizzled
    float* Bs = sm + NSTAGE * TILE_ELEMS;         // [NSTAGE][128][32] swizzled (n-major)

    const int tid  = threadIdx.x;
    const int warp = tid >> 5;
    const int lane = tid & 31;
    const int wm = warp & 3;
    const int wn = warp >> 2;
    const int g  = lane >> 2;
    const int tg = lane & 3;
    const int row0 = blockIdx.y * 128;
    const int col0 = blockIdx.x * 128;

    // fill indices: each thread covers 4 rows (stride 32), one 16B granule per row
    const int fr = tid >> 3;            // 0..31
    const int fg = tid & 7;             // granule 0..7

    // per-lane fragment rows
    int arow[2], brow[4];
#pragma unroll
    for (int mi = 0; mi < 2; mi++)
        arow[mi] = wm * 32 + mi * 16 + ((lane >> 3) & 1) * 8 + (lane & 7);
#pragma unroll
    for (int p = 0; p < 4; p++)
        brow[p] = wn * 64 + p * 16 + ((lane >> 4) & 1) * 8 + (lane & 7);
    const int aghi = lane >> 4;         // 0/1 granule offset within k-tile
    const int bghi = (lane >> 3) & 1;

    float c[2][8][4];
#pragma unroll
    for (int mi = 0; mi < 2; mi++)
#pragma unroll
        for (int ni = 0; ni < 8; ni++)
#pragma unroll
            for (int q = 0; q < 4; q++) c[mi][ni][q] = 0.0f;

    const int KT = K >> 5;

    auto fill = [&](int s, int kt) {
        float* as = As + s * TILE_ELEMS;
        float* bs = Bs + s * TILE_ELEMS;
#pragma unroll
        for (int it = 0; it < 4; it++) {
            int r = fr + it * 32;
            int sg = fg ^ (r & 7);
            int sz = (row0 + r < M) ? 16 : 0;
            cp16(as + r * 32 + sg * 4, A + (size_t)(row0 + r) * K + kt + fg * 4, sz);
        }
#pragma unroll
        for (int it = 0; it < 4; it++) {
            int r = fr + it * 32;
            int sg = fg ^ (r & 7);
            cp16(bs + r * 32 + sg * 4, WT + (size_t)(col0 + r) * K + kt + fg * 4, 16);
        }
    };

    fill(0, 0);
    cp_commit();
    if (KT > 1) fill(1, 32);
    cp_commit();

    for (int kti = 0; kti < KT; kti++) {
        cp_wait1();
        __syncthreads();
        {
            int nx = kti + 2;
            if (nx < KT) fill(nx % NSTAGE, nx * 32);
            cp_commit();
        }

        const float* as = As + (kti % NSTAGE) * TILE_ELEMS;
        const float* bs = Bs + (kti % NSTAGE) * TILE_ELEMS;
#pragma unroll
        for (int ks = 0; ks < 4; ks++) {
            unsigned a[2][4], b[8][2];
#pragma unroll
            for (int mi = 0; mi < 2; mi++) {
                int r = arow[mi];
                int gr = (2 * ks + aghi) ^ (r & 7);
                ldsm4(a[mi][0], a[mi][1], a[mi][2], a[mi][3], as + r * 32 + gr * 4);
                if (CVT_A) {
#pragma unroll
                    for (int q = 0; q < 4; q++)
                        a[mi][q] = rna(__uint_as_float(a[mi][q]));
                }
            }
#pragma unroll
            for (int p = 0; p < 4; p++) {
                int r = brow[p];
                int gr = (2 * ks + bghi) ^ (r & 7);
                ldsm4(b[2 * p][0], b[2 * p][1], b[2 * p + 1][0], b[2 * p + 1][1],
                      bs + r * 32 + gr * 4);
            }
#pragma unroll
            for (int mi = 0; mi < 2; mi++)
#pragma unroll
                for (int ni = 0; ni < 8; ni++)
                    mma_tf32(c[mi][ni][0], c[mi][ni][1], c[mi][ni][2], c[mi][ni][3],
                             a[mi][0], a[mi][1], a[mi][2], a[mi][3],
                             b[ni][0], b[ni][1]);
        }
        __syncthreads();
    }

#pragma unroll
    for (int mi = 0; mi < 2; mi++) {
        int r0 = row0 + wm * 32 + mi * 16 + g;
#pragma unroll
        for (int ni = 0; ni < 8; ni++) {
            int cc = col0 + wn * 64 + ni * 8 + 2 * tg;
            if (r0 < M) {
                C[(size_t)r0 * N + cc]     = c[mi][ni][0];
                C[(size_t)r0 * N + cc + 1] = c[mi][ni][1];
            }
            if (r0 + 8 < M) {
                C[(size_t)(r0 + 8) * N + cc]     = c[mi][ni][2];
                C[(size_t)(r0 + 8) * N + cc + 1] = c[mi][ni][3];
            }
        }
    }
}

__global__ void k_gemm1(const float* __restrict__ X) {
    gemm_body<true>(X, g_W1T, g_H1, NN, H1F, INF);
}
__global__ void k_gemm2() {
    gemm_body<false>(g_A1, g_W2T, g_H2, NN, H2F, H1F);
}

// ---------------- fused CSR aggregate + self-loop + bias + leakyReLU (float4) ----------------
// one block per node, C/4 threads, each thread owns 4 channels.
template <int C, bool ROUND>
__device__ __forceinline__ void agg_body(const float* __restrict__ H,
                                         const float* __restrict__ bias,
                                         float* __restrict__ Out) {
    const int CH = C / 4;
    const int n   = blockIdx.x;
    const int tid = threadIdx.x;
    const int beg = g_rowptr[n];
    const int end = g_rowptr[n + 1];
    const float4* H4 = (const float4*)H;

    float dv = g_dinv[n];
    float s = dv * dv;
    float4 h = __ldg(&H4[(size_t)n * CH + tid]);
    float4 a0 = make_float4(h.x * s, h.y * s, h.z * s, h.w * s);
    float4 a1 = make_float4(0.f, 0.f, 0.f, 0.f);
    float4 a2 = a1, a3 = a1;

    int j = beg;
    for (; j + 4 <= end; j += 4) {
        int s0 = __ldg(&g_csrc[j]);
        int s1 = __ldg(&g_csrc[j + 1]);
        int s2 = __ldg(&g_csrc[j + 2]);
        int s3 = __ldg(&g_csrc[j + 3]);
        float c0 = __ldg(&g_ccoef[j]);
        float c1 = __ldg(&g_ccoef[j + 1]);
        float c2 = __ldg(&g_ccoef[j + 2]);
        float c3 = __ldg(&g_ccoef[j + 3]);
        float4 v0 = __ldg(&H4[(size_t)s0 * CH + tid]);
        float4 v1 = __ldg(&H4[(size_t)s1 * CH + tid]);
        float4 v2 = __ldg(&H4[(size_t)s2 * CH + tid]);
        float4 v3 = __ldg(&H4[(size_t)s3 * CH + tid]);
        a0.x += c0 * v0.x; a0.y += c0 * v0.y; a0.z += c0 * v0.z; a0.w += c0 * v0.w;
        a1.x += c1 * v1.x; a1.y += c1 * v1.y; a1.z += c1 * v1.z; a1.w += c1 * v1.w;
        a2.x += c2 * v2.x; a2.y += c2 * v2.y; a2.z += c2 * v2.z; a2.w += c2 * v2.w;
        a3.x += c3 * v3.x; a3.y += c3 * v3.y; a3.z += c3 * v3.z; a3.w += c3 * v3.w;
    }
    for (; j < end; j++) {
        float cf = __ldg(&g_ccoef[j]);
        float4 v = __ldg(&H4[(size_t)__ldg(&g_csrc[j]) * CH + tid]);
        a0.x += cf * v.x; a0.y += cf * v.y; a0.z += cf * v.z; a0.w += cf * v.w;
    }

    float4 bb = __ldg(&((const float4*)bias)[tid]);
    float4 r;
    r.x = (a0.x + a1.x) + (a2.x + a3.x) + bb.x;
    r.y = (a0.y + a1.y) + (a2.y + a3.y) + bb.y;
    r.z = (a0.z + a1.z) + (a2.z + a3.z) + bb.z;
    r.w = (a0.w + a1.w) + (a2.w + a3.w) + bb.w;
    r.x = r.x > 0.f ? r.x : r.x * NEG;
    r.y = r.y > 0.f ? r.y : r.y * NEG;
    r.z = r.z > 0.f ? r.z : r.z * NEG;
    r.w = r.w > 0.f ? r.w : r.w * NEG;
    if (ROUND) {
        r.x = __uint_as_float(rna(r.x));
        r.y = __uint_as_float(rna(r.y));
        r.z = __uint_as_float(rna(r.z));
        r.w = __uint_as_float(rna(r.w));
    }
    ((float4*)Out)[(size_t)n * CH + tid] = r;
}

__global__ void k_agg1(const float* __restrict__ b) { agg_body<H1F, true>(g_H1, b, g_A1); }
__global__ void k_agg2(const float* __restrict__ b, float* __restrict__ out) {
    agg_body<H2F, false>(g_H2, b, out);
}

// ---------------- launch (single stream; gemm1 at launch index 3 for ncu) ----------------
extern "C" void kernel_launch(void* const* d_in, const int* in_sizes, int n_in,
                              void* d_out, int out_size) {
    const float* X  = (const float*)d_in[0];
    const int*   ew = (const int*)d_in[1];
    const float* W1 = (const float*)d_in[2];
    const float* b1 = (const float*)d_in[3];
    const float* W2 = (const float*)d_in[4];
    const float* b2 = (const float*)d_in[5];
    float* out = (float*)d_out;

    cudaFuncSetAttribute(k_gemm1, cudaFuncAttributeMaxDynamicSharedMemorySize, GEMM_SMEM);
    cudaFuncSetAttribute(k_gemm2, cudaFuncAttributeMaxDynamicSharedMemorySize, GEMM_SMEM);

    const int T = 256;
    k_zerodet<<<NBLK, T>>>(ew);                      // 0
    k_hist<<<(EE + T - 1) / T, T>>>(ew);             // 1
    k_wt<<<(INF * H1F + T - 1) / T, T>>>(W1, W2);    // 2

    dim3 g1(H1F / 128, (NN + 127) / 128);
    k_gemm1<<<g1, 256, GEMM_SMEM>>>(X);              // 3  <- ncu capture point

    k_scan1<<<NBLK, T>>>();                          // 4
    k_scan23<<<NBLK, T>>>();                         // 5
    k_place<<<(EE + T - 1) / T, T>>>(ew);            // 6

    k_agg1<<<NN, H1F / 4>>>(b1);                     // 7

    dim3 g2(H2F / 128, (NN + 127) / 128);
    k_gemm2<<<g2, 256, GEMM_SMEM>>>();               // 8
    k_agg2<<<NN, H2F / 4>>>(b2, out);                // 9
}